// round 2
// baseline (speedup 1.0000x reference)
#include <cuda_runtime.h>

// MonarchOutProjection: out[t][i*32+j] = sum_m R[j][i][m] * h2[t][m][j]
//                       h2[t][b][n]    = sum_m L[b][n][m] * x[t][m*32+b]
// Two-stage, each stage a batched 32x32x32 block GEMM over 32768 tokens.
//
// Stage kernels are persistent (grid = #SMs), hold the transposed 128KB
// weight matrix in shared memory (loaded once per CTA), and stream 16-token
// tiles. All hot-loop shared accesses are bank-conflict-free via pad-33 /
// pad-17 layouts. Intermediate h2 lives in a __device__ scratch array.

#define NTHREADS 256
#define TILE_T   16

// 32768 tokens * 1024 floats scratch for the stage-1 output.
// Layout: g_h2[t*1024 + n*32 + b] = h2[t][b][n]
__device__ float g_h2[33554432];

// Shared layouts:
//  Lt[n][m][b] : idx = n*1056 + m*33 + b      (32*33 = 1056)
//  Rt[i][m][j] : idx = i*1056 + m*33 + j
//  xs[c][t]    : idx = c*17 + t               (c in [0,1024), t in [0,16))
//  os[n][t][b] : idx = n*528 + t*33 + b       (16*33 = 528)  -- aliases xs
//  ws[m][t][j] : idx = m*528 + t*33 + j
#define WMAT_FLOATS 33792            // 32*1056
#define SMEM_BYTES  204800           // (33792 + 17408) * 4

__global__ __launch_bounds__(NTHREADS, 1)
void monarch_stage1(const float* __restrict__ x, const float* __restrict__ L,
                    int ntiles) {
    extern __shared__ float sm[];
    float* Lt = sm;                      // [n][m][b]
    float* xs = sm + WMAT_FLOATS;        // [c][t]  (aliased by os after barrier)

    const int tid  = threadIdx.x;
    const int warp = tid >> 5;
    const int lane = tid & 31;           // lane = b (block index)

    // Load L transposed: Lt[n][m][b] = L[b][n][m]. Gmem reads coalesced over m.
    for (int i = tid; i < 32768; i += NTHREADS) {
        int m = i & 31, n = (i >> 5) & 31, b = i >> 10;
        Lt[n * 1056 + m * 33 + b] = L[b * 1024 + n * 32 + m];
    }
    __syncthreads();

    for (int tile = blockIdx.x; tile < ntiles; tile += gridDim.x) {
        const int t0 = tile * TILE_T;

        // Load + transpose x tile: xs[c][t] = x[t0+t][c].
        // Gmem coalesced (c fast); STS lanes stride 17 -> conflict-free.
        for (int i = tid; i < TILE_T * 1024; i += NTHREADS) {
            int c = i & 1023, t = i >> 10;
            xs[c * 17 + t] = x[(t0 + t) * 1024 + c];
        }
        __syncthreads();

        // Compute: warp handles n in [4*warp, 4*warp+4); lane = b.
        float acc[4][TILE_T];
        #pragma unroll
        for (int q = 0; q < 4; q++)
            #pragma unroll
            for (int t = 0; t < TILE_T; t++) acc[q][t] = 0.0f;

        const float* LtW = Lt + (warp * 4) * 1056 + lane;
        #pragma unroll 4
        for (int m = 0; m < 32; m++) {
            float lv[4];
            #pragma unroll
            for (int q = 0; q < 4; q++) lv[q] = LtW[q * 1056 + m * 33];
            const float* xp = xs + (m * 32 + lane) * 17;
            float xv[TILE_T];
            #pragma unroll
            for (int t = 0; t < TILE_T; t++) xv[t] = xp[t];
            #pragma unroll
            for (int q = 0; q < 4; q++)
                #pragma unroll
                for (int t = 0; t < TILE_T; t++)
                    acc[q][t] = fmaf(lv[q], xv[t], acc[q][t]);
        }
        __syncthreads();   // all xs reads done before aliasing as os

        // Stage results: os[n][t][b] = acc. Lanes consecutive -> conflict-free.
        #pragma unroll
        for (int q = 0; q < 4; q++)
            #pragma unroll
            for (int t = 0; t < TILE_T; t++)
                xs[(warp * 4 + q) * 528 + t * 33 + lane] = acc[q][t];
        __syncthreads();

        // Coalesced writeout: g_h2[t][n*32+b] = h2[t][b][n].
        for (int i = tid; i < TILE_T * 1024; i += NTHREADS) {
            int b = i & 31, n = (i >> 5) & 31, t = i >> 10;
            g_h2[(t0 + t) * 1024 + n * 32 + b] = xs[n * 528 + t * 33 + b];
        }
        __syncthreads();   // protect xs before next tile's load
    }
}

__global__ __launch_bounds__(NTHREADS, 1)
void monarch_stage2(const float* __restrict__ R, float* __restrict__ out,
                    int ntiles) {
    extern __shared__ float sm[];
    float* Rt = sm;                      // [i][m][j]
    float* ws = sm + WMAT_FLOATS;        // [m][t][j]

    const int tid  = threadIdx.x;
    const int warp = tid >> 5;
    const int lane = tid & 31;           // lane = j (block index)

    // Load R transposed: Rt[i][m][j] = R[j][i][m]. Gmem coalesced over m.
    for (int idx = tid; idx < 32768; idx += NTHREADS) {
        int m = idx & 31, i2 = (idx >> 5) & 31, j = idx >> 10;
        Rt[i2 * 1056 + m * 33 + j] = R[j * 1024 + i2 * 32 + m];
    }
    __syncthreads();

    for (int tile = blockIdx.x; tile < ntiles; tile += gridDim.x) {
        const int t0 = tile * TILE_T;

        // Load stage-1 result: ws[m][t][j] = g_h2[t][j*32+m] (= h2[t][m][j]).
        // Gmem coalesced (m fast, then j); STS lanes stride 528 -> 2-way only.
        for (int i = tid; i < TILE_T * 1024; i += NTHREADS) {
            int m = i & 31, j = (i >> 5) & 31, t = i >> 10;
            ws[m * 528 + t * 33 + j] = g_h2[(t0 + t) * 1024 + j * 32 + m];
        }
        __syncthreads();

        // Compute: warp handles i in [4*warp, 4*warp+4); lane = j.
        float acc[4][TILE_T];
        #pragma unroll
        for (int q = 0; q < 4; q++)
            #pragma unroll
            for (int t = 0; t < TILE_T; t++) acc[q][t] = 0.0f;

        const float* RtW = Rt + (warp * 4) * 1056 + lane;
        #pragma unroll 4
        for (int m = 0; m < 32; m++) {
            float rv[4];
            #pragma unroll
            for (int q = 0; q < 4; q++) rv[q] = RtW[q * 1056 + m * 33];
            const float* wp = ws + m * 528 + lane;
            float wv[TILE_T];
            #pragma unroll
            for (int t = 0; t < TILE_T; t++) wv[t] = wp[t * 33];
            #pragma unroll
            for (int q = 0; q < 4; q++)
                #pragma unroll
                for (int t = 0; t < TILE_T; t++)
                    acc[q][t] = fmaf(rv[q], wv[t], acc[q][t]);
        }

        // Direct coalesced store: out[t][ (4w+q)*32 + j ], lanes = j consecutive.
        #pragma unroll
        for (int q = 0; q < 4; q++)
            #pragma unroll
            for (int t = 0; t < TILE_T; t++)
                out[(t0 + t) * 1024 + (warp * 4 + q) * 32 + lane] = acc[q][t];
        __syncthreads();   // protect ws before next tile's load
    }
}

extern "C" void kernel_launch(void* const* d_in, const int* in_sizes, int n_in,
                              void* d_out, int out_size) {
    const float* x = (const float*)d_in[0];
    const float* L = (const float*)d_in[1];
    const float* R = (const float*)d_in[2];
    float* out = (float*)d_out;

    const int ntok   = in_sizes[0] / 1024;   // 32768
    const int ntiles = ntok / TILE_T;        // 2048

    cudaFuncSetAttribute(monarch_stage1,
                         cudaFuncAttributeMaxDynamicSharedMemorySize, SMEM_BYTES);
    cudaFuncSetAttribute(monarch_stage2,
                         cudaFuncAttributeMaxDynamicSharedMemorySize, SMEM_BYTES);

    int sms = 148;
    cudaDeviceGetAttribute(&sms, cudaDevAttrMultiProcessorCount, 0);
    int grid = (sms < ntiles) ? sms : ntiles;

    monarch_stage1<<<grid, NTHREADS, SMEM_BYTES>>>(x, L, ntiles);
    monarch_stage2<<<grid, NTHREADS, SMEM_BYTES>>>(R, out, ntiles);
}

// round 3
// speedup vs baseline: 2.0624x; 2.0624x over previous
#include <cuda_runtime.h>

// MonarchOutProjection:
//   h2[t][b][n]    = sum_m L[b][n][m] * x[t][m*32+b]
//   out[t][i*32+j] = sum_m R[j][i][m] * h2[t][m][j]
//
// Two persistent kernels. Weights live in REGISTERS (warp = block index,
// lane = output row -> each thread holds W[blk][lane][0..31] = 32 regs).
// Smem holds only the 16-token activation tile, laid out [blk][m][t] so the
// hot loop does lane-uniform broadcast LDS.128 (4 tokens/load).
// 512-thread CTAs, 2 CTAs/SM -> 32 warps/SM.

#define TILE_T 16
#define HROW   516            // per-block row: 32*16 + 4 pad (16B-aligned, lane stride 4 banks)
#define S_TILE_FLOATS 8256    // 16 * 516
#define S2_OS_FLOATS  8704    // 32 * 272  (os[i][t][jl], row 16*17)
#define SMEM_BYTES (S2_OS_FLOATS * 4)   // 34816; covers both kernels

// Scratch: g_h2[t*1024 + b*32 + n] = h2[t][b][n]
__device__ float g_h2[33554432];

__global__ __launch_bounds__(512, 2)
void monarch_stage1(const float* __restrict__ x, const float* __restrict__ L,
                    int ntiles) {
    extern __shared__ float sm[];        // xs[bl][m][t] : bl*516 + m*16 + t
    const int tid  = threadIdx.x;
    const int warp = tid >> 5;           // bl in [0,16)
    const int lane = tid & 31;           // n
    const int half   = blockIdx.x & 1;
    const int bstart = half * 16;
    const int b      = bstart + warp;

    // Weights into registers: Lreg[m] = L[b][n=lane][m]
    float Lreg[32];
    const float4* Lp = (const float4*)(L + b * 1024 + lane * 32);
    #pragma unroll
    for (int q = 0; q < 8; q++) {
        float4 v = Lp[q];
        Lreg[4*q+0] = v.x; Lreg[4*q+1] = v.y; Lreg[4*q+2] = v.z; Lreg[4*q+3] = v.w;
    }

    const int tstride = gridDim.x >> 1;
    for (int tile = blockIdx.x >> 1; tile < ntiles; tile += tstride) {
        const int t0 = tile * TILE_T;

        // Load tile: xs[bl][m][t] = x[t0+t][m*32 + bstart + bl]
        for (int i = tid; i < 16 * 32 * TILE_T; i += 512) {
            int bl = i & 15, m = (i >> 4) & 31, t = i >> 9;
            sm[bl * HROW + m * 16 + t] = x[(t0 + t) * 1024 + m * 32 + bstart + bl];
        }
        __syncthreads();

        float acc[TILE_T];
        #pragma unroll
        for (int t = 0; t < TILE_T; t++) acc[t] = 0.0f;

        const float4* xp = (const float4*)(sm + warp * HROW);  // lane-uniform
        #pragma unroll
        for (int m = 0; m < 32; m++) {
            #pragma unroll
            for (int t4 = 0; t4 < 4; t4++) {
                float4 xv = xp[m * 4 + t4];                    // broadcast LDS.128
                acc[t4*4+0] = fmaf(Lreg[m], xv.x, acc[t4*4+0]);
                acc[t4*4+1] = fmaf(Lreg[m], xv.y, acc[t4*4+1]);
                acc[t4*4+2] = fmaf(Lreg[m], xv.z, acc[t4*4+2]);
                acc[t4*4+3] = fmaf(Lreg[m], xv.w, acc[t4*4+3]);
            }
        }

        // Coalesced store: g_h2[t][b*32+n], lanes consecutive.
        float* op = g_h2 + t0 * 1024 + b * 32 + lane;
        #pragma unroll
        for (int t = 0; t < TILE_T; t++) op[t * 1024] = acc[t];
        __syncthreads();
    }
}

__global__ __launch_bounds__(512, 2)
void monarch_stage2(const float* __restrict__ R, float* __restrict__ out,
                    int ntiles) {
    extern __shared__ float sm[];        // hs[jl][m][t] ; later aliased as os[i][t][jl]
    const int tid  = threadIdx.x;
    const int warp = tid >> 5;           // jl in [0,16)
    const int lane = tid & 31;           // i
    const int half   = blockIdx.x & 1;
    const int jstart = half * 16;
    const int j      = jstart + warp;

    // Weights: Rreg[m] = R[j][i=lane][m]
    float Rreg[32];
    const float4* Rp = (const float4*)(R + j * 1024 + lane * 32);
    #pragma unroll
    for (int q = 0; q < 8; q++) {
        float4 v = Rp[q];
        Rreg[4*q+0] = v.x; Rreg[4*q+1] = v.y; Rreg[4*q+2] = v.z; Rreg[4*q+3] = v.w;
    }

    const int tstride = gridDim.x >> 1;
    for (int tile = blockIdx.x >> 1; tile < ntiles; tile += tstride) {
        const int t0 = tile * TILE_T;

        // Load: hs[jl][m][t] = h2[t][m][j] = g_h2[t][m*32 + j]
        for (int i = tid; i < 16 * 32 * TILE_T; i += 512) {
            int jl = i & 15, m = (i >> 4) & 31, t = i >> 9;
            sm[jl * HROW + m * 16 + t] = g_h2[(t0 + t) * 1024 + m * 32 + jstart + jl];
        }
        __syncthreads();

        float acc[TILE_T];
        #pragma unroll
        for (int t = 0; t < TILE_T; t++) acc[t] = 0.0f;

        const float4* hp = (const float4*)(sm + warp * HROW);
        #pragma unroll
        for (int m = 0; m < 32; m++) {
            #pragma unroll
            for (int t4 = 0; t4 < 4; t4++) {
                float4 hv = hp[m * 4 + t4];
                acc[t4*4+0] = fmaf(Rreg[m], hv.x, acc[t4*4+0]);
                acc[t4*4+1] = fmaf(Rreg[m], hv.y, acc[t4*4+1]);
                acc[t4*4+2] = fmaf(Rreg[m], hv.z, acc[t4*4+2]);
                acc[t4*4+3] = fmaf(Rreg[m], hv.w, acc[t4*4+3]);
            }
        }
        __syncthreads();   // hs reads done; alias smem as os

        // Stage: os[i][t][jl] = acc  (addr = i*272 + t*17 + jl; lane=i stride
        // 272 -> 2-way; readers conflict-free)
        #pragma unroll
        for (int t = 0; t < TILE_T; t++)
            sm[lane * 272 + t * 17 + warp] = acc[t];
        __syncthreads();

        // Coalesced writeout: out[t][i*32 + jstart + jl]
        for (int i3 = tid; i3 < 16 * 32 * TILE_T; i3 += 512) {
            int jl = i3 & 15, i = (i3 >> 4) & 31, t = i3 >> 9;
            out[(t0 + t) * 1024 + i * 32 + jstart + jl] = sm[i * 272 + t * 17 + jl];
        }
        __syncthreads();
    }
}

extern "C" void kernel_launch(void* const* d_in, const int* in_sizes, int n_in,
                              void* d_out, int out_size) {
    const float* x = (const float*)d_in[0];
    const float* L = (const float*)d_in[1];
    const float* R = (const float*)d_in[2];
    float* out = (float*)d_out;

    const int ntok   = in_sizes[0] / 1024;   // 32768
    const int ntiles = ntok / TILE_T;        // 2048

    int sms = 148;
    cudaDeviceGetAttribute(&sms, cudaDevAttrMultiProcessorCount, 0);
    int grid = 2 * sms;                      // (tile-half) pairs; half = bid&1

    monarch_stage1<<<grid, 512, SMEM_BYTES>>>(x, L, ntiles);
    monarch_stage2<<<grid, 512, SMEM_BYTES>>>(R, out, ntiles);
}

// round 4
// speedup vs baseline: 2.0640x; 1.0008x over previous
#include <cuda_runtime.h>

// MonarchOutProjection:
//   h2[t][b][n]    = sum_m L[b][n][m] * x[t][m*32+b]
//   out[t][i*32+j] = sum_m R[j][i][m] * h2[t][m][j]
//
// Two persistent kernels, weights in registers (warp = block, lane = out row,
// 32 weight regs/thread). R3: cp.async double-buffered tile loads so the
// global->shared copy for tile k+1 overlaps compute on tile k; no exposed
// DRAM latency per tile. 512-thread CTAs, 2 CTAs/SM (32 warps/SM).

#define TILE_T 16
#define HROW   516              // 32*16 + 4 pad (float4-aligned, 4-bank lane stride)
#define BUF_FLOATS 8256         // 16 * 516
#define OS_FLOATS  8704         // 32 * 272 (os[i][t][jl], row 16*17)

#define SMEM1_BYTES (2 * BUF_FLOATS * 4)                 // 66048
#define SMEM2_BYTES ((2 * BUF_FLOATS + OS_FLOATS) * 4)   // 100864

// Scratch: g_h2[t*1024 + b*32 + n] = h2[t][b][n]
__device__ float g_h2[33554432];

__device__ __forceinline__ unsigned smem_addr(const void* p) {
    return (unsigned)__cvta_generic_to_shared(p);
}
__device__ __forceinline__ void cp_async4(unsigned dst, const float* src) {
    asm volatile("cp.async.ca.shared.global [%0], [%1], 4;" :: "r"(dst), "l"(src));
}
__device__ __forceinline__ void cp_commit() {
    asm volatile("cp.async.commit_group;");
}
__device__ __forceinline__ void cp_wait1() {
    asm volatile("cp.async.wait_group 1;");
}

__global__ __launch_bounds__(512, 2)
void monarch_stage1(const float* __restrict__ x, const float* __restrict__ L,
                    int ntiles) {
    extern __shared__ float sm[];        // buf0 | buf1 : xs[bl][m][t]
    const int tid  = threadIdx.x;
    const int warp = tid >> 5;           // bl in [0,16)
    const int lane = tid & 31;           // n
    const int half   = blockIdx.x & 1;
    const int bstart = half * 16;
    const int b      = bstart + warp;

    // Weights: Lreg[m] = L[b][n=lane][m]
    float Lreg[32];
    const float4* Lp = (const float4*)(L + b * 1024 + lane * 32);
    #pragma unroll
    for (int q = 0; q < 8; q++) {
        float4 v = Lp[q];
        Lreg[4*q+0] = v.x; Lreg[4*q+1] = v.y; Lreg[4*q+2] = v.z; Lreg[4*q+3] = v.w;
    }

    const unsigned sbase = smem_addr(sm);
    const int tstride = gridDim.x >> 1;
    const int tile0   = blockIdx.x >> 1;

    // Per-thread copy indices (fixed across tiles): 16 elements/thread.
    const int cbl = tid & 15, cm = (tid >> 4) & 31;   // i = tid + k*512 -> t = k + base
    const int ct0 = tid >> 9;                          // 0 (tid<512)

    // Prologue: async-load tile0 into buf0.
    if (tile0 < ntiles) {
        const float* srcb = x + (tile0 * TILE_T) * 1024 + cm * 32 + bstart + cbl;
        unsigned dstb = sbase + (cbl * HROW + cm * 16 + ct0) * 4;
        #pragma unroll
        for (int k = 0; k < 16; k++)
            cp_async4(dstb + k * 4, srcb + k * 1024);
    }
    cp_commit();

    int cur = 0;
    for (int tile = tile0; tile < ntiles; tile += tstride) {
        // Issue next tile's copy into the other buffer.
        int nxt = tile + tstride;
        if (nxt < ntiles) {
            const float* srcb = x + (nxt * TILE_T) * 1024 + cm * 32 + bstart + cbl;
            unsigned dstb = sbase + ((cur ^ 1) * BUF_FLOATS + cbl * HROW + cm * 16 + ct0) * 4;
            #pragma unroll
            for (int k = 0; k < 16; k++)
                cp_async4(dstb + k * 4, srcb + k * 1024);
        }
        cp_commit();
        cp_wait1();          // current tile's group complete
        __syncthreads();

        float acc[TILE_T];
        #pragma unroll
        for (int t = 0; t < TILE_T; t++) acc[t] = 0.0f;

        const float4* xp = (const float4*)(sm + cur * BUF_FLOATS + warp * HROW);
        #pragma unroll
        for (int m = 0; m < 32; m++) {
            #pragma unroll
            for (int t4 = 0; t4 < 4; t4++) {
                float4 xv = xp[m * 4 + t4];            // broadcast LDS.128
                acc[t4*4+0] = fmaf(Lreg[m], xv.x, acc[t4*4+0]);
                acc[t4*4+1] = fmaf(Lreg[m], xv.y, acc[t4*4+1]);
                acc[t4*4+2] = fmaf(Lreg[m], xv.z, acc[t4*4+2]);
                acc[t4*4+3] = fmaf(Lreg[m], xv.w, acc[t4*4+3]);
            }
        }
        __syncthreads();     // buf[cur] reads done before it is refilled

        // Coalesced store: g_h2[t][b*32+n].
        float* op = g_h2 + tile * TILE_T * 1024 + b * 32 + lane;
        #pragma unroll
        for (int t = 0; t < TILE_T; t++) op[t * 1024] = acc[t];

        cur ^= 1;
    }
}

__global__ __launch_bounds__(512, 2)
void monarch_stage2(const float* __restrict__ R, float* __restrict__ out,
                    int ntiles) {
    extern __shared__ float sm[];        // buf0 | buf1 : hs[jl][m][t] ; then os
    float* os = sm + 2 * BUF_FLOATS;     // os[i][t][jl] : i*272 + t*17 + jl
    const int tid  = threadIdx.x;
    const int warp = tid >> 5;           // jl in [0,16)
    const int lane = tid & 31;           // i
    const int half   = blockIdx.x & 1;
    const int jstart = half * 16;
    const int j      = jstart + warp;

    // Weights: Rreg[m] = R[j][i=lane][m]
    float Rreg[32];
    const float4* Rp = (const float4*)(R + j * 1024 + lane * 32);
    #pragma unroll
    for (int q = 0; q < 8; q++) {
        float4 v = Rp[q];
        Rreg[4*q+0] = v.x; Rreg[4*q+1] = v.y; Rreg[4*q+2] = v.z; Rreg[4*q+3] = v.w;
    }

    const unsigned sbase = smem_addr(sm);
    const int tstride = gridDim.x >> 1;
    const int tile0   = blockIdx.x >> 1;

    const int cjl = tid & 15, cm = (tid >> 4) & 31;

    // Prologue: async-load tile0 into buf0: hs[jl][m][t] = g_h2[t][m*32+j].
    if (tile0 < ntiles) {
        const float* srcb = g_h2 + (tile0 * TILE_T) * 1024 + cm * 32 + jstart + cjl;
        unsigned dstb = sbase + (cjl * HROW + cm * 16) * 4;
        #pragma unroll
        for (int k = 0; k < 16; k++)
            cp_async4(dstb + k * 4, srcb + k * 1024);
    }
    cp_commit();

    int cur = 0;
    for (int tile = tile0; tile < ntiles; tile += tstride) {
        int nxt = tile + tstride;
        if (nxt < ntiles) {
            const float* srcb = g_h2 + (nxt * TILE_T) * 1024 + cm * 32 + jstart + cjl;
            unsigned dstb = sbase + ((cur ^ 1) * BUF_FLOATS + cjl * HROW + cm * 16) * 4;
            #pragma unroll
            for (int k = 0; k < 16; k++)
                cp_async4(dstb + k * 4, srcb + k * 1024);
        }
        cp_commit();
        cp_wait1();
        __syncthreads();

        float acc[TILE_T];
        #pragma unroll
        for (int t = 0; t < TILE_T; t++) acc[t] = 0.0f;

        const float4* hp = (const float4*)(sm + cur * BUF_FLOATS + warp * HROW);
        #pragma unroll
        for (int m = 0; m < 32; m++) {
            #pragma unroll
            for (int t4 = 0; t4 < 4; t4++) {
                float4 hv = hp[m * 4 + t4];
                acc[t4*4+0] = fmaf(Rreg[m], hv.x, acc[t4*4+0]);
                acc[t4*4+1] = fmaf(Rreg[m], hv.y, acc[t4*4+1]);
                acc[t4*4+2] = fmaf(Rreg[m], hv.z, acc[t4*4+2]);
                acc[t4*4+3] = fmaf(Rreg[m], hv.w, acc[t4*4+3]);
            }
        }
        __syncthreads();     // buf[cur] reads done; os from prev writeout done

        // Stage for coalesced output: os[i=lane][t][jl=warp].
        #pragma unroll
        for (int t = 0; t < TILE_T; t++)
            os[lane * 272 + t * 17 + warp] = acc[t];
        __syncthreads();

        // Coalesced writeout: out[t][i*32 + jstart + jl].
        const int t0 = tile * TILE_T;
        for (int i3 = tid; i3 < 16 * 32 * TILE_T; i3 += 512) {
            int jl = i3 & 15, i = (i3 >> 4) & 31, t = i3 >> 9;
            out[(t0 + t) * 1024 + i * 32 + jstart + jl] = os[i * 272 + t * 17 + jl];
        }
        __syncthreads();     // os reads done before next tile's os writes

        cur ^= 1;
    }
}

extern "C" void kernel_launch(void* const* d_in, const int* in_sizes, int n_in,
                              void* d_out, int out_size) {
    const float* x = (const float*)d_in[0];
    const float* L = (const float*)d_in[1];
    const float* R = (const float*)d_in[2];
    float* out = (float*)d_out;

    const int ntok   = in_sizes[0] / 1024;   // 32768
    const int ntiles = ntok / TILE_T;        // 2048

    cudaFuncSetAttribute(monarch_stage1,
                         cudaFuncAttributeMaxDynamicSharedMemorySize, SMEM1_BYTES);
    cudaFuncSetAttribute(monarch_stage2,
                         cudaFuncAttributeMaxDynamicSharedMemorySize, SMEM2_BYTES);

    int sms = 148;
    cudaDeviceGetAttribute(&sms, cudaDevAttrMultiProcessorCount, 0);
    int grid = 2 * sms;                      // (tile, half) pairs; half = bid&1

    monarch_stage1<<<grid, 512, SMEM1_BYTES>>>(x, L, ntiles);
    monarch_stage2<<<grid, 512, SMEM2_BYTES>>>(R, out, ntiles);
}

// round 5
// speedup vs baseline: 2.1755x; 1.0540x over previous
#include <cuda_runtime.h>
#include <cstdint>

// MonarchOutProjection:
//   h2[t][b][n]    = sum_m L[b][n][m] * x[t][m*32+b]
//   out[t][i*32+j] = sum_m R[j][i][m] * h2[t][m][j]
//
// R4: g_h2 re-laid out as [tile][n][b][t] (t contiguous) so stage1 writes
// STG.128 and stage2's tile is a contiguous 32KB block loaded with 16B
// cp.async.cg. Inner loops use packed fma.rn.f32x2 (FFMA2).

#define TILE_T 16
#define HROW   516                 // stage1 xs row: 32*16 + 4 pad
#define BUF1_FLOATS 8256           // 16 * 516
#define BUF2_FLOATS 8192           // 16 jl * 32 m * 16 t (dense)
#define OS_FLOATS   8704           // 32 * 272 (os[i][t][jl], row 16*17)

#define SMEM1_BYTES (2 * BUF1_FLOATS * 4)                  // 66048
#define SMEM2_BYTES ((2 * BUF2_FLOATS + OS_FLOATS) * 4)    // 100352

// g_h2[tile][n][b][t] : idx = tile*16384 + n*512 + b*16 + t
__device__ float g_h2[33554432];

__device__ __forceinline__ unsigned smem_addr(const void* p) {
    return (unsigned)__cvta_generic_to_shared(p);
}
__device__ __forceinline__ void cp_async4(unsigned dst, const float* src) {
    asm volatile("cp.async.ca.shared.global [%0], [%1], 4;" :: "r"(dst), "l"(src));
}
__device__ __forceinline__ void cp_async16(unsigned dst, const float* src) {
    asm volatile("cp.async.cg.shared.global [%0], [%1], 16;" :: "r"(dst), "l"(src));
}
__device__ __forceinline__ void cp_commit() {
    asm volatile("cp.async.commit_group;");
}
__device__ __forceinline__ void cp_wait1() {
    asm volatile("cp.async.wait_group 1;");
}
// acc = w2 * v2 + acc  (two independent fp32 FMAs)
__device__ __forceinline__ void ffma2(uint64_t& acc, uint64_t a, uint64_t b) {
    asm("fma.rn.f32x2 %0, %1, %2, %0;" : "+l"(acc) : "l"(a), "l"(b));
}
__device__ __forceinline__ uint64_t splat2(float w) {
    uint64_t r;
    asm("mov.b64 %0, {%1, %1};" : "=l"(r) : "f"(w));
    return r;
}

__global__ __launch_bounds__(512, 2)
void monarch_stage1(const float* __restrict__ x, const float* __restrict__ L,
                    int ntiles) {
    extern __shared__ float sm[];        // buf0|buf1 : xs[bl][m][t], row HROW
    const int tid  = threadIdx.x;
    const int warp = tid >> 5;           // bl
    const int lane = tid & 31;           // n
    const int half   = blockIdx.x & 1;
    const int bstart = half * 16;
    const int b      = bstart + warp;

    // Weights: Lreg[m] = L[b][n=lane][m]
    float Lreg[32];
    const float4* Lp = (const float4*)(L + b * 1024 + lane * 32);
    #pragma unroll
    for (int q = 0; q < 8; q++) {
        float4 v = Lp[q];
        Lreg[4*q+0] = v.x; Lreg[4*q+1] = v.y; Lreg[4*q+2] = v.z; Lreg[4*q+3] = v.w;
    }

    const unsigned sbase = smem_addr(sm);
    const int tstride = gridDim.x >> 1;
    const int tile0   = blockIdx.x >> 1;

    // Copy mapping (fixed): thread handles (cbl, cm), 16 t-values, 4B each.
    const int cbl = tid & 15, cm = (tid >> 4) & 31;

    if (tile0 < ntiles) {
        const float* srcb = x + (tile0 * TILE_T) * 1024 + cm * 32 + bstart + cbl;
        unsigned dstb = sbase + (cbl * HROW + cm * 16) * 4;
        #pragma unroll
        for (int k = 0; k < 16; k++)
            cp_async4(dstb + k * 4, srcb + k * 1024);
    }
    cp_commit();

    int cur = 0;
    for (int tile = tile0; tile < ntiles; tile += tstride) {
        int nxt = tile + tstride;
        if (nxt < ntiles) {
            const float* srcb = x + (nxt * TILE_T) * 1024 + cm * 32 + bstart + cbl;
            unsigned dstb = sbase + ((cur ^ 1) * BUF1_FLOATS + cbl * HROW + cm * 16) * 4;
            #pragma unroll
            for (int k = 0; k < 16; k++)
                cp_async4(dstb + k * 4, srcb + k * 1024);
        }
        cp_commit();
        cp_wait1();
        __syncthreads();

        uint64_t acc2[8];
        #pragma unroll
        for (int t = 0; t < 8; t++) acc2[t] = 0ull;

        const ulonglong2* xq =
            (const ulonglong2*)(sm + cur * BUF1_FLOATS + warp * HROW);  // lane-uniform
        #pragma unroll
        for (int m = 0; m < 32; m++) {
            uint64_t w2 = splat2(Lreg[m]);
            #pragma unroll
            for (int k = 0; k < 4; k++) {
                ulonglong2 xv = xq[m * 4 + k];       // broadcast LDS.128 = 4 t
                ffma2(acc2[2*k+0], w2, xv.x);
                ffma2(acc2[2*k+1], w2, xv.y);
            }
        }
        __syncthreads();     // buf[cur] reads done before refill

        // STG.128 x4: g_h2[tile][n=lane][b][t], t-contiguous per thread.
        ulonglong2* op = (ulonglong2*)(g_h2 + tile * 16384 + (lane * 32 + b) * 16);
        #pragma unroll
        for (int k = 0; k < 4; k++) {
            ulonglong2 v; v.x = acc2[2*k]; v.y = acc2[2*k+1];
            op[k] = v;
        }

        cur ^= 1;
    }
}

__global__ __launch_bounds__(512, 2)
void monarch_stage2(const float* __restrict__ R, float* __restrict__ out,
                    int ntiles) {
    extern __shared__ float sm[];        // buf0|buf1 : hs[jl][m][t] dense ; then os
    float* os = sm + 2 * BUF2_FLOATS;    // os[i][t][jl] : i*272 + t*17 + jl
    const int tid  = threadIdx.x;
    const int warp = tid >> 5;           // jl
    const int lane = tid & 31;           // i
    const int half   = blockIdx.x & 1;
    const int jstart = half * 16;
    const int j      = jstart + warp;

    // Weights: Rreg[m] = R[j][i=lane][m]
    float Rreg[32];
    const float4* Rp = (const float4*)(R + j * 1024 + lane * 32);
    #pragma unroll
    for (int q = 0; q < 8; q++) {
        float4 v = Rp[q];
        Rreg[4*q+0] = v.x; Rreg[4*q+1] = v.y; Rreg[4*q+2] = v.z; Rreg[4*q+3] = v.w;
    }

    const unsigned sbase = smem_addr(sm);
    const int tstride = gridDim.x >> 1;
    const int tile0   = blockIdx.x >> 1;

    // Tile for this half is contiguous: g_h2 + tile*16384 + jstart*512, 8192 floats.
    // Each thread copies 4 x 16B, fully coalesced.
    if (tile0 < ntiles) {
        const float4* srcb = (const float4*)(g_h2 + tile0 * 16384 + jstart * 512);
        #pragma unroll
        for (int k = 0; k < 4; k++)
            cp_async16(sbase + (tid + k * 512) * 16, (const float*)(srcb + tid + k * 512));
    }
    cp_commit();

    int cur = 0;
    for (int tile = tile0; tile < ntiles; tile += tstride) {
        int nxt = tile + tstride;
        if (nxt < ntiles) {
            const float4* srcb = (const float4*)(g_h2 + nxt * 16384 + jstart * 512);
            unsigned dstb = sbase + (cur ^ 1) * BUF2_FLOATS * 4;
            #pragma unroll
            for (int k = 0; k < 4; k++)
                cp_async16(dstb + (tid + k * 512) * 16, (const float*)(srcb + tid + k * 512));
        }
        cp_commit();
        cp_wait1();
        __syncthreads();

        uint64_t acc2[8];
        #pragma unroll
        for (int t = 0; t < 8; t++) acc2[t] = 0ull;

        const ulonglong2* hq =
            (const ulonglong2*)(sm + cur * BUF2_FLOATS + warp * 512);  // lane-uniform
        #pragma unroll
        for (int m = 0; m < 32; m++) {
            uint64_t w2 = splat2(Rreg[m]);
            #pragma unroll
            for (int k = 0; k < 4; k++) {
                ulonglong2 hv = hq[m * 4 + k];       // broadcast LDS.128
                ffma2(acc2[2*k+0], w2, hv.x);
                ffma2(acc2[2*k+1], w2, hv.y);
            }
        }
        __syncthreads();     // buf[cur] reads done; prev os readout done

        // Stage: os[i=lane][t][jl=warp] (lane stride 272 -> 2-way STS).
        #pragma unroll
        for (int k = 0; k < 8; k++) {
            float2 p; *(uint64_t*)&p = acc2[k];
            os[lane * 272 + (2*k+0) * 17 + warp] = p.x;
            os[lane * 272 + (2*k+1) * 17 + warp] = p.y;
        }
        __syncthreads();

        // Coalesced writeout: out[t][i*32 + jstart + jl].
        const int t0 = tile * TILE_T;
        for (int i3 = tid; i3 < 16 * 32 * TILE_T; i3 += 512) {
            int jl = i3 & 15, i = (i3 >> 4) & 31, t = i3 >> 9;
            out[(t0 + t) * 1024 + i * 32 + jstart + jl] = os[i * 272 + t * 17 + jl];
        }
        __syncthreads();     // os reads done before next tile's writes

        cur ^= 1;
    }
}

extern "C" void kernel_launch(void* const* d_in, const int* in_sizes, int n_in,
                              void* d_out, int out_size) {
    const float* x = (const float*)d_in[0];
    const float* L = (const float*)d_in[1];
    const float* R = (const float*)d_in[2];
    float* out = (float*)d_out;

    const int ntok   = in_sizes[0] / 1024;   // 32768
    const int ntiles = ntok / TILE_T;        // 2048

    cudaFuncSetAttribute(monarch_stage1,
                         cudaFuncAttributeMaxDynamicSharedMemorySize, SMEM1_BYTES);
    cudaFuncSetAttribute(monarch_stage2,
                         cudaFuncAttributeMaxDynamicSharedMemorySize, SMEM2_BYTES);

    int sms = 148;
    cudaDeviceGetAttribute(&sms, cudaDevAttrMultiProcessorCount, 0);
    int grid = 2 * sms;

    monarch_stage1<<<grid, 512, SMEM1_BYTES>>>(x, L, ntiles);
    monarch_stage2<<<grid, 512, SMEM2_BYTES>>>(R, out, ntiles);
}

// round 6
// speedup vs baseline: 2.1758x; 1.0001x over previous
#include <cuda_runtime.h>
#include <cstdint>

// MonarchOutProjection:
//   h2[t][b][n]    = sum_m L[b][n][m] * x[t][m*32+b]
//   out[t][i*32+j] = sum_m R[j][i][m] * h2[t][m][j]
//
// R4: g_h2 re-laid out as [tile][n][b][t] (t contiguous) so stage1 writes
// STG.128 and stage2's tile is a contiguous 32KB block loaded with 16B
// cp.async.cg. Inner loops use packed fma.rn.f32x2 (FFMA2).

#define TILE_T 16
#define HROW   516                 // stage1 xs row: 32*16 + 4 pad
#define BUF1_FLOATS 8256           // 16 * 516
#define BUF2_FLOATS 8192           // 16 jl * 32 m * 16 t (dense)
#define OS_FLOATS   8704           // 32 * 272 (os[i][t][jl], row 16*17)

#define SMEM1_BYTES (2 * BUF1_FLOATS * 4)                  // 66048
#define SMEM2_BYTES ((2 * BUF2_FLOATS + OS_FLOATS) * 4)    // 100352

// g_h2[tile][n][b][t] : idx = tile*16384 + n*512 + b*16 + t
__device__ float g_h2[33554432];

__device__ __forceinline__ unsigned smem_addr(const void* p) {
    return (unsigned)__cvta_generic_to_shared(p);
}
__device__ __forceinline__ void cp_async4(unsigned dst, const float* src) {
    asm volatile("cp.async.ca.shared.global [%0], [%1], 4;" :: "r"(dst), "l"(src));
}
__device__ __forceinline__ void cp_async16(unsigned dst, const float* src) {
    asm volatile("cp.async.cg.shared.global [%0], [%1], 16;" :: "r"(dst), "l"(src));
}
__device__ __forceinline__ void cp_commit() {
    asm volatile("cp.async.commit_group;");
}
__device__ __forceinline__ void cp_wait1() {
    asm volatile("cp.async.wait_group 1;");
}
// acc = w2 * v2 + acc  (two independent fp32 FMAs)
__device__ __forceinline__ void ffma2(uint64_t& acc, uint64_t a, uint64_t b) {
    asm("fma.rn.f32x2 %0, %1, %2, %0;" : "+l"(acc) : "l"(a), "l"(b));
}
__device__ __forceinline__ uint64_t splat2(float w) {
    uint64_t r;
    asm("mov.b64 %0, {%1, %1};" : "=l"(r) : "f"(w));
    return r;
}

__global__ __launch_bounds__(512, 2)
void monarch_stage1(const float* __restrict__ x, const float* __restrict__ L,
                    int ntiles) {
    extern __shared__ float sm[];        // buf0|buf1 : xs[bl][m][t], row HROW
    const int tid  = threadIdx.x;
    const int warp = tid >> 5;           // bl
    const int lane = tid & 31;           // n
    const int half   = blockIdx.x & 1;
    const int bstart = half * 16;
    const int b      = bstart + warp;

    // Weights: Lreg[m] = L[b][n=lane][m]
    float Lreg[32];
    const float4* Lp = (const float4*)(L + b * 1024 + lane * 32);
    #pragma unroll
    for (int q = 0; q < 8; q++) {
        float4 v = Lp[q];
        Lreg[4*q+0] = v.x; Lreg[4*q+1] = v.y; Lreg[4*q+2] = v.z; Lreg[4*q+3] = v.w;
    }

    const unsigned sbase = smem_addr(sm);
    const int tstride = gridDim.x >> 1;
    const int tile0   = blockIdx.x >> 1;

    // Copy mapping (fixed): thread handles (cbl, cm), 16 t-values, 4B each.
    const int cbl = tid & 15, cm = (tid >> 4) & 31;

    if (tile0 < ntiles) {
        const float* srcb = x + (tile0 * TILE_T) * 1024 + cm * 32 + bstart + cbl;
        unsigned dstb = sbase + (cbl * HROW + cm * 16) * 4;
        #pragma unroll
        for (int k = 0; k < 16; k++)
            cp_async4(dstb + k * 4, srcb + k * 1024);
    }
    cp_commit();

    int cur = 0;
    for (int tile = tile0; tile < ntiles; tile += tstride) {
        int nxt = tile + tstride;
        if (nxt < ntiles) {
            const float* srcb = x + (nxt * TILE_T) * 1024 + cm * 32 + bstart + cbl;
            unsigned dstb = sbase + ((cur ^ 1) * BUF1_FLOATS + cbl * HROW + cm * 16) * 4;
            #pragma unroll
            for (int k = 0; k < 16; k++)
                cp_async4(dstb + k * 4, srcb + k * 1024);
        }
        cp_commit();
        cp_wait1();
        __syncthreads();

        uint64_t acc2[8];
        #pragma unroll
        for (int t = 0; t < 8; t++) acc2[t] = 0ull;

        const ulonglong2* xq =
            (const ulonglong2*)(sm + cur * BUF1_FLOATS + warp * HROW);  // lane-uniform
        #pragma unroll
        for (int m = 0; m < 32; m++) {
            uint64_t w2 = splat2(Lreg[m]);
            #pragma unroll
            for (int k = 0; k < 4; k++) {
                ulonglong2 xv = xq[m * 4 + k];       // broadcast LDS.128 = 4 t
                ffma2(acc2[2*k+0], w2, xv.x);
                ffma2(acc2[2*k+1], w2, xv.y);
            }
        }
        __syncthreads();     // buf[cur] reads done before refill

        // STG.128 x4: g_h2[tile][n=lane][b][t], t-contiguous per thread.
        ulonglong2* op = (ulonglong2*)(g_h2 + tile * 16384 + (lane * 32 + b) * 16);
        #pragma unroll
        for (int k = 0; k < 4; k++) {
            ulonglong2 v; v.x = acc2[2*k]; v.y = acc2[2*k+1];
            op[k] = v;
        }

        cur ^= 1;
    }
}

__global__ __launch_bounds__(512, 2)
void monarch_stage2(const float* __restrict__ R, float* __restrict__ out,
                    int ntiles) {
    extern __shared__ float sm[];        // buf0|buf1 : hs[jl][m][t] dense ; then os
    float* os = sm + 2 * BUF2_FLOATS;    // os[i][t][jl] : i*272 + t*17 + jl
    const int tid  = threadIdx.x;
    const int warp = tid >> 5;           // jl
    const int lane = tid & 31;           // i
    const int half   = blockIdx.x & 1;
    const int jstart = half * 16;
    const int j      = jstart + warp;

    // Weights: Rreg[m] = R[j][i=lane][m]
    float Rreg[32];
    const float4* Rp = (const float4*)(R + j * 1024 + lane * 32);
    #pragma unroll
    for (int q = 0; q < 8; q++) {
        float4 v = Rp[q];
        Rreg[4*q+0] = v.x; Rreg[4*q+1] = v.y; Rreg[4*q+2] = v.z; Rreg[4*q+3] = v.w;
    }

    const unsigned sbase = smem_addr(sm);
    const int tstride = gridDim.x >> 1;
    const int tile0   = blockIdx.x >> 1;

    // Tile for this half is contiguous: g_h2 + tile*16384 + jstart*512, 8192 floats.
    // Each thread copies 4 x 16B, fully coalesced.
    if (tile0 < ntiles) {
        const float4* srcb = (const float4*)(g_h2 + tile0 * 16384 + jstart * 512);
        #pragma unroll
        for (int k = 0; k < 4; k++)
            cp_async16(sbase + (tid + k * 512) * 16, (const float*)(srcb + tid + k * 512));
    }
    cp_commit();

    int cur = 0;
    for (int tile = tile0; tile < ntiles; tile += tstride) {
        int nxt = tile + tstride;
        if (nxt < ntiles) {
            const float4* srcb = (const float4*)(g_h2 + nxt * 16384 + jstart * 512);
            unsigned dstb = sbase + (cur ^ 1) * BUF2_FLOATS * 4;
            #pragma unroll
            for (int k = 0; k < 4; k++)
                cp_async16(dstb + (tid + k * 512) * 16, (const float*)(srcb + tid + k * 512));
        }
        cp_commit();
        cp_wait1();
        __syncthreads();

        uint64_t acc2[8];
        #pragma unroll
        for (int t = 0; t < 8; t++) acc2[t] = 0ull;

        const ulonglong2* hq =
            (const ulonglong2*)(sm + cur * BUF2_FLOATS + warp * 512);  // lane-uniform
        #pragma unroll
        for (int m = 0; m < 32; m++) {
            uint64_t w2 = splat2(Rreg[m]);
            #pragma unroll
            for (int k = 0; k < 4; k++) {
                ulonglong2 hv = hq[m * 4 + k];       // broadcast LDS.128
                ffma2(acc2[2*k+0], w2, hv.x);
                ffma2(acc2[2*k+1], w2, hv.y);
            }
        }
        __syncthreads();     // buf[cur] reads done; prev os readout done

        // Stage: os[i=lane][t][jl=warp] (lane stride 272 -> 2-way STS).
        #pragma unroll
        for (int k = 0; k < 8; k++) {
            float2 p; *(uint64_t*)&p = acc2[k];
            os[lane * 272 + (2*k+0) * 17 + warp] = p.x;
            os[lane * 272 + (2*k+1) * 17 + warp] = p.y;
        }
        __syncthreads();

        // Coalesced writeout: out[t][i*32 + jstart + jl].
        const int t0 = tile * TILE_T;
        for (int i3 = tid; i3 < 16 * 32 * TILE_T; i3 += 512) {
            int jl = i3 & 15, i = (i3 >> 4) & 31, t = i3 >> 9;
            out[(t0 + t) * 1024 + i * 32 + jstart + jl] = os[i * 272 + t * 17 + jl];
        }
        __syncthreads();     // os reads done before next tile's writes

        cur ^= 1;
    }
}

extern "C" void kernel_launch(void* const* d_in, const int* in_sizes, int n_in,
                              void* d_out, int out_size) {
    const float* x = (const float*)d_in[0];
    const float* L = (const float*)d_in[1];
    const float* R = (const float*)d_in[2];
    float* out = (float*)d_out;

    const int ntok   = in_sizes[0] / 1024;   // 32768
    const int ntiles = ntok / TILE_T;        // 2048

    cudaFuncSetAttribute(monarch_stage1,
                         cudaFuncAttributeMaxDynamicSharedMemorySize, SMEM1_BYTES);
    cudaFuncSetAttribute(monarch_stage2,
                         cudaFuncAttributeMaxDynamicSharedMemorySize, SMEM2_BYTES);

    int sms = 148;
    cudaDeviceGetAttribute(&sms, cudaDevAttrMultiProcessorCount, 0);
    int grid = 2 * sms;

    monarch_stage1<<<grid, 512, SMEM1_BYTES>>>(x, L, ntiles);
    monarch_stage2<<<grid, 512, SMEM2_BYTES>>>(R, out, ntiles);
}